// round 14
// baseline (speedup 1.0000x reference)
#include <cuda_runtime.h>

#define BATCH   64
#define NCLS    80
#define RM      16
#define NO      144      // 80 + 4*16
#define A0      6400     // 80x80
#define A1      1600     // 40x40
#define A2      400      // 20x20
#define AT      8400
#define MAXDET  300
#define ADJW    12       // padded words per adjacency row (10 used)

typedef unsigned long long ull;

__device__ float g_conf[BATCH * AT];
__device__ int   g_label[BATCH * AT];
__device__ ull   g_topkey[BATCH * MAXDET];
__device__ float4 g_bcorn[BATCH * MAXDET];   // x1,y1,x2,y2 (class-offset)
__device__ float4 g_bbox [BATCH * MAXDET];   // cx,cy,w,h
__device__ float4 g_bmeta[BATCH * MAXDET];   // area, conf, label, 0

// ---------------------------------------------------------------------------
// K1: per-anchor class argmax + sigmoid(max), float4-vectorized.
// ---------------------------------------------------------------------------
__global__ void k_conf(const float* __restrict__ f0,
                       const float* __restrict__ f1,
                       const float* __restrict__ f2) {
    int q = blockIdx.x * blockDim.x + threadIdx.x;
    int b = blockIdx.y;
    if (q >= AT / 4) return;
    int a = q * 4;

    const float* f; int hw, loc;
    if (a < A0)            { f = f0; hw = A0; loc = a; }
    else if (a < A0 + A1)  { f = f1; hw = A1; loc = a - A0; }
    else                   { f = f2; hw = A2; loc = a - A0 - A1; }

    const float4* base = (const float4*)(f + ((size_t)b * NO + 4 * RM) * hw) + (loc >> 2);
    int hw4 = hw >> 2;

    float4 v = base[0];
    float m0 = v.x, m1 = v.y, m2 = v.z, m3 = v.w;
    int l0 = 0, l1 = 0, l2 = 0, l3 = 0;
#pragma unroll 8
    for (int c = 1; c < NCLS; ++c) {
        v = base[(size_t)c * hw4];
        if (v.x > m0) { m0 = v.x; l0 = c; }
        if (v.y > m1) { m1 = v.y; l1 = c; }
        if (v.z > m2) { m2 = v.z; l2 = c; }
        if (v.w > m3) { m3 = v.w; l3 = c; }
    }
    float4 cf;
    cf.x = 1.0f / (1.0f + __expf(-m0));
    cf.y = 1.0f / (1.0f + __expf(-m1));
    cf.z = 1.0f / (1.0f + __expf(-m2));
    cf.w = 1.0f / (1.0f + __expf(-m3));
    *(float4*)&g_conf[b * AT + a] = cf;
    int4 lb; lb.x = l0; lb.y = l1; lb.z = l2; lb.w = l3;
    *(int4*)&g_label[b * AT + a] = lb;
}

// key = (monotonic conf bits << 32) | (~index); conf>0 so mono map = |signbit.
__device__ __forceinline__ ull key_from(float c, int i) {
    unsigned ub = __float_as_uint(c) | 0x80000000u;
    return ((ull)ub << 32) | (ull)(0xFFFFFFFFu - (unsigned)i);
}

// ---------------------------------------------------------------------------
// K2: per-batch exact top-300. Radix select with direct-rank early finish;
// pass 1 fused with the global->SMEM copy. Sorted keys -> g_topkey.
// ---------------------------------------------------------------------------
__global__ void __launch_bounds__(1024, 1)
k_topk() {
    __shared__ float s_conf[AT];          // 33.6 KB
    __shared__ ull  s_dkeys[512];
    __shared__ int  s_hist[256];
    __shared__ ull  s_keys[MAXDET];
    __shared__ ull  sh_prefix;
    __shared__ int  sh_rank, sh_done, sh_cd;
    __shared__ int  s_cnt, s_nc;

    const int b    = blockIdx.x;
    const int tid  = threadIdx.x;
    const int lane = tid & 31;
    const int wid  = tid >> 5;

    if (tid == 0) {
        sh_prefix = 0ull; sh_rank = MAXDET; sh_done = 0; sh_cd = AT;
        s_cnt = 0; s_nc = 0;
    }
    if (tid < 256) s_hist[tid] = 0;
    __syncthreads();

    // pass 1 (byte [56,64)): copy global->SMEM fused with histogram
    for (int base = 0; base < AT; base += 1024) {
        int i = base + tid;
        bool in = (i < AT);
        float c = 0.0f;
        int bin = 0;
        if (in) {
            c = g_conf[b * AT + i];
            s_conf[i] = c;
            bin = (int)((__float_as_uint(c) | 0x80000000u) >> 24);
        }
        unsigned am = __ballot_sync(0xFFFFFFFFu, in);
        if (in) {
            unsigned peers = __match_any_sync(am, bin);
            if ((__ffs(peers) - 1) == lane)
                atomicAdd(&s_hist[bin], __popc(peers));
        }
    }
    __syncthreads();

    for (int shift = 56; ; shift -= 8) {
        // digit selection from s_hist (warp 0)
        if (wid == 0) {
            int base = 255 - lane * 8;
            int loc[8]; int gs = 0;
#pragma unroll
            for (int t = 0; t < 8; ++t) { loc[t] = s_hist[base - t]; gs += loc[t]; }
            int cum = gs;
#pragma unroll
            for (int o = 1; o < 32; o <<= 1) {
                int v = __shfl_up_sync(0xFFFFFFFFu, cum, o);
                if (lane >= o) cum += v;
            }
            int r = sh_rank;
            bool found = (cum >= r) && ((cum - gs) < r);
            unsigned m = __ballot_sync(0xFFFFFFFFu, found);
            int src = __ffs(m) - 1;
            if (lane == src) {
                int c = cum - gs;
                int d = base, rr = r, cd = 0;
#pragma unroll
                for (int t = 0; t < 8; ++t) {
                    c += loc[t];
                    if (c >= r) { d = base - t; cd = loc[t]; rr = r - (c - loc[t]); break; }
                }
                sh_rank   = rr;
                sh_prefix = sh_prefix | ((ull)d << shift);
                sh_cd     = cd;
                if (cd == rr) sh_done = 1;   // whole bin selected: prefix exact
            }
        }
        __syncthreads();
        if (sh_done || shift == 0) break;

        if (sh_cd <= 512) {
            // direct finish: compact actives, exact rank-by-counting; the
            // rank rr-1 key IS the exact 64-bit pivot.
            if (tid == 0) s_nc = 0;
            __syncthreads();
            ull pfx = sh_prefix;
            for (int i = tid; i < AT; i += 1024) {
                ull key = key_from(s_conf[i], i);
                if ((key >> shift) == (pfx >> shift)) {
                    int p = atomicAdd(&s_nc, 1);
                    if (p < 512) s_dkeys[p] = key;
                }
            }
            __syncthreads();
            int cd = s_nc;
            int r  = sh_rank;
            if (tid < cd) {
                ull mine = s_dkeys[tid];
                int cnt = 0;
                for (int j = 0; j < cd; ++j) cnt += (s_dkeys[j] > mine);
                if (cnt == r - 1) sh_prefix = mine;
            }
            __syncthreads();
            break;
        }

        // another radix pass among actives
        int nshift = shift - 8;
        if (tid < 256) s_hist[tid] = 0;
        __syncthreads();
        ull pfx = sh_prefix;
        for (int base = 0; base < AT; base += 1024) {
            int i = base + tid;
            bool act = false; int bin = 0;
            if (i < AT) {
                ull key = key_from(s_conf[i], i);
                act = ((key >> shift) == (pfx >> shift));
                bin = (int)((key >> nshift) & 255);
            }
            unsigned am = __ballot_sync(0xFFFFFFFFu, act);
            if (act) {
                unsigned peers = __match_any_sync(am, bin);
                if ((__ffs(peers) - 1) == lane)
                    atomicAdd(&s_hist[bin], __popc(peers));
            }
        }
        __syncthreads();
    }

    // collect exactly 300 keys >= pivot
    ull pivot = sh_prefix;
    for (int i = tid; i < AT; i += 1024) {
        ull key = key_from(s_conf[i], i);
        if (key >= pivot) {
            int p = atomicAdd(&s_cnt, 1);
            if (p < MAXDET) s_keys[p] = key;
        }
    }
    __syncthreads();

    // warp-parallel rank-by-counting -> sorted keys to global
    for (int k = wid; k < MAXDET; k += 32) {
        ull key = s_keys[k];
        int cnt = 0;
        for (int j = lane; j < MAXDET; j += 32) cnt += (s_keys[j] > key);
#pragma unroll
        for (int o = 16; o > 0; o >>= 1)
            cnt += __shfl_down_sync(0xFFFFFFFFu, cnt, o);
        if (lane == 0) g_topkey[b * MAXDET + cnt] = key;
    }
}

// ---------------------------------------------------------------------------
// K3: chip-wide DFL decode (thread per (b,box,side); 300 CTAs) + fused box
// assembly on lane s==0. Softmax without max-subtraction (scale-invariant).
// ---------------------------------------------------------------------------
__global__ void k_decode(const float* __restrict__ f0,
                         const float* __restrict__ f1,
                         const float* __restrict__ f2) {
    int t = blockIdx.x * blockDim.x + threadIdx.x;   // grid exact: BATCH*300*4
    int b   = t / (MAXDET * 4);
    int r   = t - b * (MAXDET * 4);
    int box = r >> 2, s = r & 3;
    int lane = threadIdx.x & 31;

    ull key = g_topkey[b * MAXDET + box];
    int gidx = (int)(0xFFFFFFFFu - (unsigned)(key & 0xFFFFFFFFull));

    const float* f; int hw, loc, W; float stride;
    if (gidx < A0)           { f = f0; hw = A0; loc = gidx;           W = 80; stride = 8.0f; }
    else if (gidx < A0 + A1) { f = f1; hw = A1; loc = gidx - A0;      W = 40; stride = 16.0f; }
    else                     { f = f2; hw = A2; loc = gidx - A0 - A1; W = 20; stride = 32.0f; }

    const float* p = f + (size_t)b * NO * hw + (size_t)(s * RM) * hw + loc;
    float se = 0.0f, sk = 0.0f;
#pragma unroll
    for (int k = 0; k < RM; ++k) {
        float e = __expf(__ldg(&p[(size_t)k * hw]));
        se += e;
        sk += e * (float)k;
    }
    float d = sk / se;

    int base_lane = lane & ~3;
    float d0 = __shfl_sync(0xFFFFFFFFu, d, base_lane + 0);
    float d1 = __shfl_sync(0xFFFFFFFFu, d, base_lane + 1);
    float d2 = __shfl_sync(0xFFFFFFFFu, d, base_lane + 2);
    float d3 = __shfl_sync(0xFFFFFFFFu, d, base_lane + 3);

    if (s == 0) {
        float conf = __uint_as_float((unsigned)(key >> 32) & 0x7FFFFFFFu);
        float gx = (float)(loc % W) + 0.5f;
        float gy = (float)(loc / W) + 0.5f;
        float x1 = gx - d0, y1 = gy - d1;
        float x2 = gx + d2, y2 = gy + d3;
        float cx = (x1 + x2) * 0.5f * stride;
        float cy = (y1 + y2) * 0.5f * stride;
        float w  = (x2 - x1) * stride;
        float h  = (y2 - y1) * stride;

        float lab = (float)__ldg(&g_label[b * AT + gidx]);
        float off = lab * 10000.0f;
        float bx1 = (cx - w * 0.5f) + off;
        float by1 = (cy - h * 0.5f) + off;
        float bx2 = (cx + w * 0.5f) + off;
        float by2 = (cy + h * 0.5f) + off;
        float aw = bx2 - bx1; if (aw < 0.0f) aw = 0.0f;
        float ah = by2 - by1; if (ah < 0.0f) ah = 0.0f;

        int o = b * MAXDET + box;
        g_bcorn[o] = make_float4(bx1, by1, bx2, by2);
        g_bbox [o] = make_float4(cx, cy, w, h);
        g_bmeta[o] = make_float4(aw * ah, conf, lab, 0.0f);
    }
}

// ---------------------------------------------------------------------------
// K4: class-bucketed sparse adjacency (cross-class IoU exactly 0 via the
// 10000*label offset) + sparse greedy scan + output. One CTA per batch.
// ---------------------------------------------------------------------------
__global__ void __launch_bounds__(1024, 1)
k_nms(float* __restrict__ out) {
    __shared__ float4 s_c[MAXDET];
    __shared__ float  s_a[MAXDET];
    __shared__ float  s_cf[MAXDET];
    __shared__ int    s_lab[MAXDET];
    __shared__ unsigned s_adj[MAXDET * ADJW];    // 14.4 KB, zeroed
    __shared__ unsigned s_suppw[10];
    __shared__ unsigned s_nz[10];
    __shared__ int s_ccnt[NCLS];
    __shared__ int s_cstart[NCLS];
    __shared__ int s_cpos[NCLS];
    __shared__ unsigned short s_items[MAXDET];

    const int b    = blockIdx.x;
    const int tid  = threadIdx.x;
    const int lane = tid & 31;

    for (int t = tid; t < MAXDET * ADJW / 4; t += 1024)
        ((uint4*)s_adj)[t] = make_uint4(0u, 0u, 0u, 0u);
    if (tid < NCLS) s_ccnt[tid] = 0;
    if (tid < 10)   s_nz[tid] = 0u;
    __syncthreads();

    if (tid < MAXDET) {
        s_c[tid]  = g_bcorn[b * MAXDET + tid];
        float4 mt = g_bmeta[b * MAXDET + tid];
        s_a[tid]  = mt.x;
        s_cf[tid] = mt.y;
        int lab = (int)mt.z;
        s_lab[tid] = lab;
        atomicAdd(&s_ccnt[lab], 1);
    }
    __syncthreads();

    if (tid == 0) {
        int acc = 0;
#pragma unroll
        for (int c = 0; c < NCLS; ++c) {
            s_cstart[c] = acc;
            s_cpos[c]   = acc;
            acc += s_ccnt[c];
        }
    }
    __syncthreads();

    if (tid < MAXDET) {
        int p = atomicAdd(&s_cpos[s_lab[tid]], 1);
        s_items[p] = (unsigned short)tid;
    }
    __syncthreads();

    // same-class pair IoU; set adjacency bits (row = smaller index)
    if (tid < MAXDET) {
        int lab   = s_lab[tid];
        int start = s_cstart[lab];
        int cnt   = s_ccnt[lab];
        float4 ci = s_c[tid];
        float  ai = s_a[tid];
        bool any = false;
        for (int t = 0; t < cnt; ++t) {
            int j = (int)s_items[start + t];
            if (j <= tid) continue;
            float4 cj = s_c[j];
            float ix1 = fmaxf(ci.x, cj.x);
            float iy1 = fmaxf(ci.y, cj.y);
            float ix2 = fminf(ci.z, cj.z);
            float iy2 = fminf(ci.w, cj.w);
            float iw = ix2 - ix1; if (iw < 0.0f) iw = 0.0f;
            float ih = iy2 - iy1; if (ih < 0.0f) ih = 0.0f;
            float inter = iw * ih;
            if (inter > 0.0f) {
                float iou = inter / (ai + s_a[j] - inter + 1e-7f);
                if (iou > 0.7f) {
                    atomicOr(&s_adj[tid * ADJW + (j >> 5)], 1u << (j & 31));
                    any = true;
                }
            }
        }
        if (any) atomicOr(&s_nz[tid >> 5], 1u << (tid & 31));
    }

    if (tid < 320) {
        bool sup0 = (tid < MAXDET) ? !(s_cf[tid] > 0.001f) : false;
        unsigned wv = __ballot_sync(0xFFFFFFFFu, sup0);
        if (lane == 0) s_suppw[tid >> 5] = wv;
    }
    __syncthreads();

    // sparse greedy scan
    if (tid == 0) {
        unsigned supp[10];
#pragma unroll
        for (int k = 0; k < 10; ++k) supp[k] = s_suppw[k];
#pragma unroll
        for (int w = 0; w < 10; ++w) {
            unsigned rem = s_nz[w] & ~supp[w];
            while (rem) {
                int bit = __ffs(rem) - 1;
                const uint4* r4 = (const uint4*)&s_adj[((w << 5) + bit) * ADJW];
                uint4 ra = r4[0], rb = r4[1], rc = r4[2];
                supp[0] |= ra.x; supp[1] |= ra.y; supp[2] |= ra.z; supp[3] |= ra.w;
                supp[4] |= rb.x; supp[5] |= rb.y; supp[6] |= rb.z; supp[7] |= rb.w;
                supp[8] |= rc.x; supp[9] |= rc.y;
                rem &= ~(1u << bit);
                rem &= ~supp[w];
            }
        }
#pragma unroll
        for (int k = 0; k < 10; ++k) s_suppw[k] = supp[k];
    }
    __syncthreads();

    if (tid < MAXDET) {
        bool sup = (s_suppw[tid >> 5] >> (tid & 31)) & 1u;
        float4 bb = g_bbox[b * MAXDET + tid];
        float4 mt = g_bmeta[b * MAXDET + tid];
        float conf = sup ? 0.0f : mt.y;
        float* o = out + ((size_t)b * MAXDET + tid) * 6;
        o[0] = bb.x; o[1] = bb.y; o[2] = bb.z; o[3] = bb.w;
        o[4] = conf; o[5] = mt.z;
    }
}

extern "C" void kernel_launch(void* const* d_in, const int* in_sizes, int n_in,
                              void* d_out, int out_size) {
    const float* f0 = (const float*)d_in[0];
    const float* f1 = (const float*)d_in[1];
    const float* f2 = (const float*)d_in[2];
    float* out = (float*)d_out;

    dim3 g1((AT / 4 + 255) / 256, BATCH);
    k_conf<<<g1, 256>>>(f0, f1, f2);
    k_topk<<<BATCH, 1024>>>();
    k_decode<<<BATCH * MAXDET * 4 / 256, 256>>>(f0, f1, f2);
    k_nms<<<BATCH, 1024>>>(out);
}

// round 15
// speedup vs baseline: 1.0869x; 1.0869x over previous
#include <cuda_runtime.h>

#define BATCH   64
#define NCLS    80
#define RM      16
#define NO      144      // 80 + 4*16
#define A0      6400     // 80x80
#define A1      1600     // 40x40
#define A2      400      // 20x20
#define AT      8400
#define MAXDET  300
#define ADJW    12       // padded words per adjacency row (10 used)
#define NBIN    4096
#define MAXCAND 2048

typedef unsigned long long ull;

__device__ float g_conf[BATCH * AT];
__device__ int   g_label[BATCH * AT];
__device__ int   g_hist[BATCH * NBIN];       // zero-init; k_select re-zeros
__device__ ull   g_topkey[BATCH * MAXDET];
__device__ float4 g_bcorn[BATCH * MAXDET];   // x1,y1,x2,y2 (class-offset)
__device__ float4 g_bbox [BATCH * MAXDET];   // cx,cy,w,h
__device__ float4 g_bmeta[BATCH * MAXDET];   // area, conf, label, 0

// bin: order-consistent 4096-bin coarsening of the conf order.
// conf = sigmoid(.) in (0,1); if exp==126 (conf in [0.5,1)) use top-12
// mantissa bits, else clamp to bin 0 (any exp<126 value is smaller than any
// exp==126 value, so bin order remains consistent with key order).
__device__ __forceinline__ int conf_bin(unsigned bits) {
    return ((bits >> 23) == 126u) ? (int)((bits >> 11) & 0xFFFu) : 0;
}

// key = (monotonic conf bits << 32) | (~index); conf>0 so mono map = |signbit.
__device__ __forceinline__ ull key_from(float c, int i) {
    unsigned ub = __float_as_uint(c) | 0x80000000u;
    return ((ull)ub << 32) | (ull)(0xFFFFFFFFu - (unsigned)i);
}

// ---------------------------------------------------------------------------
// K1: per-anchor class argmax + sigmoid(max), float4-vectorized; also builds
// the per-batch conf histogram (scattered global atomics, near-free).
// ---------------------------------------------------------------------------
__global__ void k_conf(const float* __restrict__ f0,
                       const float* __restrict__ f1,
                       const float* __restrict__ f2) {
    int q = blockIdx.x * blockDim.x + threadIdx.x;
    int b = blockIdx.y;
    if (q >= AT / 4) return;
    int a = q * 4;

    const float* f; int hw, loc;
    if (a < A0)            { f = f0; hw = A0; loc = a; }
    else if (a < A0 + A1)  { f = f1; hw = A1; loc = a - A0; }
    else                   { f = f2; hw = A2; loc = a - A0 - A1; }

    const float4* base = (const float4*)(f + ((size_t)b * NO + 4 * RM) * hw) + (loc >> 2);
    int hw4 = hw >> 2;

    float4 v = base[0];
    float m0 = v.x, m1 = v.y, m2 = v.z, m3 = v.w;
    int l0 = 0, l1 = 0, l2 = 0, l3 = 0;
#pragma unroll 8
    for (int c = 1; c < NCLS; ++c) {
        v = base[(size_t)c * hw4];
        if (v.x > m0) { m0 = v.x; l0 = c; }
        if (v.y > m1) { m1 = v.y; l1 = c; }
        if (v.z > m2) { m2 = v.z; l2 = c; }
        if (v.w > m3) { m3 = v.w; l3 = c; }
    }
    float4 cf;
    cf.x = 1.0f / (1.0f + __expf(-m0));
    cf.y = 1.0f / (1.0f + __expf(-m1));
    cf.z = 1.0f / (1.0f + __expf(-m2));
    cf.w = 1.0f / (1.0f + __expf(-m3));
    *(float4*)&g_conf[b * AT + a] = cf;
    int4 lb; lb.x = l0; lb.y = l1; lb.z = l2; lb.w = l3;
    *(int4*)&g_label[b * AT + a] = lb;

    int* hist = &g_hist[b * NBIN];
    atomicAdd(&hist[conf_bin(__float_as_uint(cf.x))], 1);
    atomicAdd(&hist[conf_bin(__float_as_uint(cf.y))], 1);
    atomicAdd(&hist[conf_bin(__float_as_uint(cf.z))], 1);
    atomicAdd(&hist[conf_bin(__float_as_uint(cf.w))], 1);
}

// ---------------------------------------------------------------------------
// K2: histogram-based exact top-300. One CTA per batch.
//   a) block suffix-scan over 4096 bins -> pivot bin pb
//   b) one conf scan: collect keys with bin >= pb (~300 + small)
//   c) exact rank-by-count among candidates -> sorted keys to g_topkey
//   d) re-zero the histogram for the next graph replay
// ---------------------------------------------------------------------------
__global__ void __launch_bounds__(1024, 1)
k_select() {
    __shared__ int s_wt[32];
    __shared__ int s_ws[32];
    __shared__ int s_pb;
    __shared__ ull s_cand[MAXCAND];   // 16 KB
    __shared__ int s_nc;

    const int b    = blockIdx.x;
    const int tid  = threadIdx.x;
    const int lane = tid & 31;
    const int wid  = tid >> 5;

    if (tid == 0) s_nc = 0;

    // a) read my 4 bins, block suffix-scan (descending bin order)
    int4 c4 = ((const int4*)&g_hist[b * NBIN])[tid];
    int gs = c4.x + c4.y + c4.z + c4.w;

    int suf = gs;   // inclusive suffix within warp (lanes >= lane)
#pragma unroll
    for (int o = 1; o < 32; o <<= 1) {
        int v = __shfl_down_sync(0xFFFFFFFFu, suf, o);
        if (lane < 32 - o) suf += v;
    }
    if (lane == 0) s_wt[wid] = suf;
    __syncthreads();
    if (wid == 0) {
        int own = s_wt[lane];
        int ws  = own;
#pragma unroll
        for (int o = 1; o < 32; o <<= 1) {
            int v = __shfl_down_sync(0xFFFFFFFFu, ws, o);
            if (lane < 32 - o) ws += v;
        }
        s_ws[lane] = ws - own;    // sum over warps strictly above
    }
    __syncthreads();

    // after = count of keys in bins strictly above my 4-bin group
    int after = (suf - gs) + s_ws[wid];
    {
        int cs[4]    = { c4.w, c4.z, c4.y, c4.x };             // descending
        int binid[4] = { 4*tid+3, 4*tid+2, 4*tid+1, 4*tid };
        int c = after;
#pragma unroll
        for (int t = 0; t < 4; ++t) {
            int nc = c + cs[t];
            if (c < MAXDET && nc >= MAXDET) s_pb = binid[t];   // unique crossing
            c = nc;
        }
    }

    // d) re-zero histogram (safe: pivot already derived from registers)
    ((int4*)&g_hist[b * NBIN])[tid] = make_int4(0, 0, 0, 0);
    __syncthreads();

    // b) collect candidates with bin >= pb
    int pb = s_pb;
    for (int i = tid; i < AT; i += 1024) {
        float c = g_conf[b * AT + i];
        if (conf_bin(__float_as_uint(c)) >= pb) {
            int p = atomicAdd(&s_nc, 1);
            if (p < MAXCAND) s_cand[p] = key_from(c, i);
        }
    }
    __syncthreads();

    // c) exact rank among candidates; ranks < 300 are the sorted top-300
    int n = s_nc < MAXCAND ? s_nc : MAXCAND;
    for (int k = tid; k < n; k += 1024) {
        ull key = s_cand[k];
        int rank = 0;
        for (int j = 0; j < n; ++j) rank += (s_cand[j] > key);
        if (rank < MAXDET) g_topkey[b * MAXDET + rank] = key;
    }
}

// ---------------------------------------------------------------------------
// K3: chip-wide DFL decode (thread per (b,box,side); 300 CTAs) + fused box
// assembly on lane s==0. Softmax without max-subtraction (scale-invariant).
// ---------------------------------------------------------------------------
__global__ void k_decode(const float* __restrict__ f0,
                         const float* __restrict__ f1,
                         const float* __restrict__ f2) {
    int t = blockIdx.x * blockDim.x + threadIdx.x;   // grid exact: BATCH*300*4
    int b   = t / (MAXDET * 4);
    int r   = t - b * (MAXDET * 4);
    int box = r >> 2, s = r & 3;
    int lane = threadIdx.x & 31;

    ull key = g_topkey[b * MAXDET + box];
    int gidx = (int)(0xFFFFFFFFu - (unsigned)(key & 0xFFFFFFFFull));

    const float* f; int hw, loc, W; float stride;
    if (gidx < A0)           { f = f0; hw = A0; loc = gidx;           W = 80; stride = 8.0f; }
    else if (gidx < A0 + A1) { f = f1; hw = A1; loc = gidx - A0;      W = 40; stride = 16.0f; }
    else                     { f = f2; hw = A2; loc = gidx - A0 - A1; W = 20; stride = 32.0f; }

    const float* p = f + (size_t)b * NO * hw + (size_t)(s * RM) * hw + loc;
    float se = 0.0f, sk = 0.0f;
#pragma unroll
    for (int k = 0; k < RM; ++k) {
        float e = __expf(__ldg(&p[(size_t)k * hw]));
        se += e;
        sk += e * (float)k;
    }
    float d = sk / se;

    int base_lane = lane & ~3;
    float d0 = __shfl_sync(0xFFFFFFFFu, d, base_lane + 0);
    float d1 = __shfl_sync(0xFFFFFFFFu, d, base_lane + 1);
    float d2 = __shfl_sync(0xFFFFFFFFu, d, base_lane + 2);
    float d3 = __shfl_sync(0xFFFFFFFFu, d, base_lane + 3);

    if (s == 0) {
        float conf = __uint_as_float((unsigned)(key >> 32) & 0x7FFFFFFFu);
        float gx = (float)(loc % W) + 0.5f;
        float gy = (float)(loc / W) + 0.5f;
        float x1 = gx - d0, y1 = gy - d1;
        float x2 = gx + d2, y2 = gy + d3;
        float cx = (x1 + x2) * 0.5f * stride;
        float cy = (y1 + y2) * 0.5f * stride;
        float w  = (x2 - x1) * stride;
        float h  = (y2 - y1) * stride;

        float lab = (float)__ldg(&g_label[b * AT + gidx]);
        float off = lab * 10000.0f;
        float bx1 = (cx - w * 0.5f) + off;
        float by1 = (cy - h * 0.5f) + off;
        float bx2 = (cx + w * 0.5f) + off;
        float by2 = (cy + h * 0.5f) + off;
        float aw = bx2 - bx1; if (aw < 0.0f) aw = 0.0f;
        float ah = by2 - by1; if (ah < 0.0f) ah = 0.0f;

        int o = b * MAXDET + box;
        g_bcorn[o] = make_float4(bx1, by1, bx2, by2);
        g_bbox [o] = make_float4(cx, cy, w, h);
        g_bmeta[o] = make_float4(aw * ah, conf, lab, 0.0f);
    }
}

// ---------------------------------------------------------------------------
// K4: class-bucketed sparse adjacency (cross-class IoU exactly 0 via the
// 10000*label offset) + sparse greedy scan + output. One CTA per batch.
// ---------------------------------------------------------------------------
__global__ void __launch_bounds__(1024, 1)
k_nms(float* __restrict__ out) {
    __shared__ float4 s_c[MAXDET];
    __shared__ float  s_a[MAXDET];
    __shared__ float  s_cf[MAXDET];
    __shared__ int    s_lab[MAXDET];
    __shared__ unsigned s_adj[MAXDET * ADJW];    // 14.4 KB, zeroed
    __shared__ unsigned s_suppw[10];
    __shared__ unsigned s_nz[10];
    __shared__ int s_ccnt[NCLS];
    __shared__ int s_cstart[NCLS];
    __shared__ int s_cpos[NCLS];
    __shared__ unsigned short s_items[MAXDET];

    const int b    = blockIdx.x;
    const int tid  = threadIdx.x;
    const int lane = tid & 31;

    for (int t = tid; t < MAXDET * ADJW / 4; t += 1024)
        ((uint4*)s_adj)[t] = make_uint4(0u, 0u, 0u, 0u);
    if (tid < NCLS) s_ccnt[tid] = 0;
    if (tid < 10)   s_nz[tid] = 0u;
    __syncthreads();

    if (tid < MAXDET) {
        s_c[tid]  = g_bcorn[b * MAXDET + tid];
        float4 mt = g_bmeta[b * MAXDET + tid];
        s_a[tid]  = mt.x;
        s_cf[tid] = mt.y;
        int lab = (int)mt.z;
        s_lab[tid] = lab;
        atomicAdd(&s_ccnt[lab], 1);
    }
    __syncthreads();

    if (tid == 0) {
        int acc = 0;
#pragma unroll
        for (int c = 0; c < NCLS; ++c) {
            s_cstart[c] = acc;
            s_cpos[c]   = acc;
            acc += s_ccnt[c];
        }
    }
    __syncthreads();

    if (tid < MAXDET) {
        int p = atomicAdd(&s_cpos[s_lab[tid]], 1);
        s_items[p] = (unsigned short)tid;
    }
    __syncthreads();

    if (tid < MAXDET) {
        int lab   = s_lab[tid];
        int start = s_cstart[lab];
        int cnt   = s_ccnt[lab];
        float4 ci = s_c[tid];
        float  ai = s_a[tid];
        bool any = false;
        for (int t = 0; t < cnt; ++t) {
            int j = (int)s_items[start + t];
            if (j <= tid) continue;
            float4 cj = s_c[j];
            float ix1 = fmaxf(ci.x, cj.x);
            float iy1 = fmaxf(ci.y, cj.y);
            float ix2 = fminf(ci.z, cj.z);
            float iy2 = fminf(ci.w, cj.w);
            float iw = ix2 - ix1; if (iw < 0.0f) iw = 0.0f;
            float ih = iy2 - iy1; if (ih < 0.0f) ih = 0.0f;
            float inter = iw * ih;
            if (inter > 0.0f) {
                float iou = inter / (ai + s_a[j] - inter + 1e-7f);
                if (iou > 0.7f) {
                    atomicOr(&s_adj[tid * ADJW + (j >> 5)], 1u << (j & 31));
                    any = true;
                }
            }
        }
        if (any) atomicOr(&s_nz[tid >> 5], 1u << (tid & 31));
    }

    if (tid < 320) {
        bool sup0 = (tid < MAXDET) ? !(s_cf[tid] > 0.001f) : false;
        unsigned wv = __ballot_sync(0xFFFFFFFFu, sup0);
        if (lane == 0) s_suppw[tid >> 5] = wv;
    }
    __syncthreads();

    if (tid == 0) {
        unsigned supp[10];
#pragma unroll
        for (int k = 0; k < 10; ++k) supp[k] = s_suppw[k];
#pragma unroll
        for (int w = 0; w < 10; ++w) {
            unsigned rem = s_nz[w] & ~supp[w];
            while (rem) {
                int bit = __ffs(rem) - 1;
                const uint4* r4 = (const uint4*)&s_adj[((w << 5) + bit) * ADJW];
                uint4 ra = r4[0], rb = r4[1], rc = r4[2];
                supp[0] |= ra.x; supp[1] |= ra.y; supp[2] |= ra.z; supp[3] |= ra.w;
                supp[4] |= rb.x; supp[5] |= rb.y; supp[6] |= rb.z; supp[7] |= rb.w;
                supp[8] |= rc.x; supp[9] |= rc.y;
                rem &= ~(1u << bit);
                rem &= ~supp[w];
            }
        }
#pragma unroll
        for (int k = 0; k < 10; ++k) s_suppw[k] = supp[k];
    }
    __syncthreads();

    if (tid < MAXDET) {
        bool sup = (s_suppw[tid >> 5] >> (tid & 31)) & 1u;
        float4 bb = g_bbox[b * MAXDET + tid];
        float4 mt = g_bmeta[b * MAXDET + tid];
        float conf = sup ? 0.0f : mt.y;
        float* o = out + ((size_t)b * MAXDET + tid) * 6;
        o[0] = bb.x; o[1] = bb.y; o[2] = bb.z; o[3] = bb.w;
        o[4] = conf; o[5] = mt.z;
    }
}

extern "C" void kernel_launch(void* const* d_in, const int* in_sizes, int n_in,
                              void* d_out, int out_size) {
    const float* f0 = (const float*)d_in[0];
    const float* f1 = (const float*)d_in[1];
    const float* f2 = (const float*)d_in[2];
    float* out = (float*)d_out;

    dim3 g1((AT / 4 + 255) / 256, BATCH);
    k_conf<<<g1, 256>>>(f0, f1, f2);
    k_select<<<BATCH, 1024>>>();
    k_decode<<<BATCH * MAXDET * 4 / 256, 256>>>(f0, f1, f2);
    k_nms<<<BATCH, 1024>>>(out);
}